// round 1
// baseline (speedup 1.0000x reference)
#include <cuda_runtime.h>
#include <cuda_bf16.h>

// Problem constants
#define NBAT 1024
#define TT   128
#define NS   12
#define NC   4
#define NN   16   // NS + NC

// Quu element accessor (Quu = Qt[12:16,12:16])
#define QUU(x,y) sQt[(12+(x))*16 + 12 + (y)]

__global__ __launch_bounds__(256) void lqr_kernel(
    const float* __restrict__ x_init,     // [NB, NS]
    const float* __restrict__ current_u,  // [NB, T, NC]
    const float* __restrict__ Qg,         // [NB, T, N, N]
    const float* __restrict__ pg,         // [NB, T, N]
    const float* __restrict__ Ag,         // [NB, T, NS, NS]
    const float* __restrict__ Bg,         // [NB, T, NS, NC]
    float* __restrict__ out)              // [xs | us | cost]
{
    const int b   = blockIdx.x;
    const int tid = threadIdx.x;
    const size_t bT = (size_t)b * TT;

    __shared__ float sQ[256], sA[144], sB[48], sp[16], scu[4];
    __shared__ float sV[144], sv[12];
    __shared__ float sM[192], sqt[16];
    __shared__ float sQt[256];
    __shared__ float scof[16];
    __shared__ float sKt[48], skt[4];
    __shared__ float sU[48], sw[4];
    __shared__ float sk_all[TT * NC];
    __shared__ float sxu[16], sx[12], sxn[12], sr[16];

    // ---- init value function V=0, v=0 ----
    if (tid < 144) sV[tid] = 0.f;
    if (tid < 12)  sv[tid] = 0.f;

    // ---- prologue: prefetch step T-1 into registers ----
    float rQ, rX = 0.f;
    {
        const size_t t = TT - 1;
        rQ = Qg[(bT + t) * 256 + tid];
        if (tid < 144)      rX = Ag[(bT + t) * 144 + tid];
        else if (tid < 192) rX = Bg[(bT + t) * 48 + (tid - 144)];
        else if (tid < 208) rX = pg[(bT + t) * 16 + (tid - 192)];
    }
    __syncthreads();

    // ================= BACKWARD SCAN (t = T-1 .. 0) =================
    for (int t = TT - 1; t >= 0; --t) {
        // stage current step's data from registers to smem
        sQ[tid] = rQ;
        if (tid < 144)      sA[tid]       = rX;
        else if (tid < 192) sB[tid - 144] = rX;
        else if (tid < 208) sp[tid - 192] = rX;
        // prefetch next (t-1) step while we compute this one
        if (t > 0) {
            const size_t tp = t - 1;
            rQ = Qg[(bT + tp) * 256 + tid];
            if (tid < 144)      rX = Ag[(bT + tp) * 144 + tid];
            else if (tid < 192) rX = Bg[(bT + tp) * 48 + (tid - 144)];
            else if (tid < 208) rX = pg[(bT + tp) * 16 + (tid - 192)];
        }
        __syncthreads();  // s1: staged data visible; prev-iter sV/sv writes visible

        // phase 2: M = V @ F (12x16) ; qt = p + F^T v (16)
        if (tid < 192) {
            int i = tid >> 4, j = tid & 15;
            float s = 0.f;
            #pragma unroll
            for (int k = 0; k < 12; ++k) {
                float f = (j < 12) ? sA[k * 12 + j] : sB[k * 4 + (j - 12)];
                s += sV[i * 12 + k] * f;
            }
            sM[tid] = s;
        } else if (tid < 208) {
            int j = tid - 192;
            float s = sp[j];
            #pragma unroll
            for (int k = 0; k < 12; ++k) {
                float f = (j < 12) ? sA[k * 12 + j] : sB[k * 4 + (j - 12)];
                s += f * sv[k];
            }
            sqt[j] = s;
        }
        __syncthreads();  // s2

        // phase 3: Qt = Q0 + F^T M  (16x16, all 256 threads)
        {
            int i = tid >> 4, j = tid & 15;
            float s = sQ[tid];
            #pragma unroll
            for (int k = 0; k < 12; ++k) {
                float f = (i < 12) ? sA[k * 12 + i] : sB[k * 4 + (i - 12)];
                s += f * sM[k * 16 + j];
            }
            sQt[tid] = s;
        }
        __syncthreads();  // s3

        // phase 4: signed cofactors of Quu (16 threads, one each)
        if (tid < 16) {
            int a = tid >> 2, c = tid & 3;
            int r0 = (a == 0) ? 1 : 0, r1 = (a <= 1) ? 2 : 1, r2 = (a <= 2) ? 3 : 2;
            int c0 = (c == 0) ? 1 : 0, c1 = (c <= 1) ? 2 : 1, c2 = (c <= 2) ? 3 : 2;
            float m = QUU(r0, c0) * (QUU(r1, c1) * QUU(r2, c2) - QUU(r1, c2) * QUU(r2, c1))
                    - QUU(r0, c1) * (QUU(r1, c0) * QUU(r2, c2) - QUU(r1, c2) * QUU(r2, c0))
                    + QUU(r0, c2) * (QUU(r1, c0) * QUU(r2, c1) - QUU(r1, c1) * QUU(r2, c0));
            scof[tid] = ((a + c) & 1) ? -m : m;
        }
        __syncthreads();  // s4

        // phase 5: Kt = -Quu^-1 Qux (4x12) ; kt = -Quu^-1 qu (4)
        //          inv = cof^T / det (det computed redundantly per thread)
        if (tid < 52) {
            float det = 0.f;
            #pragma unroll
            for (int bb = 0; bb < 4; ++bb) det += QUU(0, bb) * scof[bb];
            float invdet = 1.0f / det;
            if (tid < 48) {
                int a = tid / 12, j = tid - a * 12;
                float s = 0.f;
                #pragma unroll
                for (int bb = 0; bb < 4; ++bb)
                    s += scof[bb * 4 + a] * sQt[(12 + bb) * 16 + j];
                sKt[tid] = -invdet * s;
            } else {
                int a = tid - 48;
                float s = 0.f;
                #pragma unroll
                for (int bb = 0; bb < 4; ++bb)
                    s += scof[bb * 4 + a] * sqt[12 + bb];
                skt[a] = -invdet * s;
            }
        }
        __syncthreads();  // s5

        // phase 6: U = Quu @ Kt ; w = qu + Quu @ kt ; stash k_t
        if (tid < 48) {
            int a = tid / 12, j = tid - a * 12;
            float s = 0.f;
            #pragma unroll
            for (int bb = 0; bb < 4; ++bb)
                s += QUU(a, bb) * sKt[bb * 12 + j];
            sU[tid] = s;
        } else if (tid < 52) {
            int a = tid - 48;
            float s = sqt[12 + a];
            #pragma unroll
            for (int bb = 0; bb < 4; ++bb)
                s += QUU(a, bb) * skt[bb];
            sw[a] = s;
        } else if (tid < 56) {
            sk_all[t * 4 + (tid - 52)] = skt[tid - 52];
        }
        __syncthreads();  // s6

        // phase 7: Vn -> sV (in place; next read is after s1), vn -> sv
        if (tid < 144) {
            int i = tid / 12, j = tid - (tid / 12) * 12;
            float s = sQt[i * 16 + j];
            #pragma unroll
            for (int a = 0; a < 4; ++a)
                s += sQt[i * 16 + 12 + a] * sKt[a * 12 + j];
            #pragma unroll
            for (int a = 0; a < 4; ++a)
                s += sKt[a * 12 + i] * (sQt[(12 + a) * 16 + j] + sU[a * 12 + j]);
            sV[tid] = s;
        } else if (tid < 156) {
            int i = tid - 144;
            float s = sqt[i];
            #pragma unroll
            for (int a = 0; a < 4; ++a)
                s += sQt[i * 16 + 12 + a] * skt[a];
            #pragma unroll
            for (int a = 0; a < 4; ++a)
                s += sKt[a * 12 + i] * sw[a];
            sv[i] = s;
        }
        // no barrier needed: next loop-top staging touches disjoint smem,
        // and s1 orders these writes before their next readers.
    }

    // ================= FORWARD SCAN (t = 0 .. T-1) =================
    float cost = 0.f;  // thread 0 accumulates
    if (tid < 12) sx[tid] = x_init[b * 12 + tid];
    {   // prefetch t = 0
        rQ = Qg[bT * 256 + tid];
        if (tid < 144)      rX = Ag[bT * 144 + tid];
        else if (tid < 192) rX = Bg[bT * 48 + (tid - 144)];
        else if (tid < 208) rX = pg[bT * 16 + (tid - 192)];
        else if (tid < 212) rX = current_u[bT * 4 + (tid - 208)];
    }

    float* out_xs   = out;
    float* out_us   = out + (size_t)NBAT * TT * NS;
    float* out_cost = out + (size_t)NBAT * TT * NS + (size_t)NBAT * TT * NC;

    for (int t = 0; t < TT; ++t) {
        sQ[tid] = rQ;
        if (tid < 144)      sA[tid]        = rX;
        else if (tid < 192) sB[tid - 144]  = rX;
        else if (tid < 208) sp[tid - 192]  = rX;
        else if (tid < 212) scu[tid - 208] = rX;
        if (t + 1 < TT) {
            const size_t tn = t + 1;
            rQ = Qg[(bT + tn) * 256 + tid];
            if (tid < 144)      rX = Ag[(bT + tn) * 144 + tid];
            else if (tid < 192) rX = Bg[(bT + tn) * 48 + (tid - 144)];
            else if (tid < 208) rX = pg[(bT + tn) * 16 + (tid - 192)];
            else if (tid < 212) rX = current_u[(bT + tn) * 4 + (tid - 208)];
        }
        __syncthreads();  // f1

        // xu = [x; u],  u = cu + k ; write xs, us outputs
        if (tid < 12) {
            sxu[tid] = sx[tid];
            out_xs[(bT + t) * 12 + tid] = sx[tid];
        } else if (tid < 16) {
            int a = tid - 12;
            float u = scu[a] + sk_all[t * 4 + a];
            sxu[tid] = u;
            out_us[(bT + t) * 4 + a] = u;
        }
        __syncthreads();  // f2

        // cost partials r[i] = xu_i * (0.5 * (Q xu)_i + p_i) ; xnext = A x + B u
        if (tid < 16) {
            float y = 0.f;
            #pragma unroll
            for (int j = 0; j < 16; ++j)
                y += sQ[tid * 16 + j] * sxu[j];
            sr[tid] = sxu[tid] * (0.5f * y + sp[tid]);
        } else if (tid < 28) {
            int i = tid - 16;
            float s = 0.f;
            #pragma unroll
            for (int j = 0; j < 12; ++j)
                s += sA[i * 12 + j] * sxu[j];
            #pragma unroll
            for (int a = 0; a < 4; ++a)
                s += sB[i * 4 + a] * sxu[12 + a];
            sxn[i] = s;
        }
        __syncthreads();  // f3

        if (tid == 0) {
            float c = 0.f;
            #pragma unroll
            for (int i = 0; i < 16; ++i) c += sr[i];
            cost += c;
        }
        if (tid < 12) sx[tid] = sxn[tid];
        // f1 of next iteration orders these writes before their readers.
    }

    if (tid == 0) out_cost[b] = cost;
}

extern "C" void kernel_launch(void* const* d_in, const int* in_sizes, int n_in,
                              void* d_out, int out_size) {
    // metadata order: x_init, current_x(unused), current_u, Q, p, A, Bmat, time(unused)
    const float* x_init    = (const float*)d_in[0];
    const float* current_u = (const float*)d_in[2];
    const float* Q         = (const float*)d_in[3];
    const float* p         = (const float*)d_in[4];
    const float* A         = (const float*)d_in[5];
    const float* Bmat      = (const float*)d_in[6];
    float* out = (float*)d_out;

    lqr_kernel<<<NBAT, 256>>>(x_init, current_u, Q, p, A, Bmat, out);
}